// round 8
// baseline (speedup 1.0000x reference)
#include <cuda_runtime.h>
#include <cstdint>

#define FDIM   1024
#define FV     256            // float4 per row
#define DDOM   8
#define NSEG   296            // 2 CTAs/SM x 148 SMs -> all co-resident
#define MAXR   64             // max rows per segment (ceil(16384/296)=56)
#define EPSV   1e-5f

// ---------------- scratch ----------------
__device__ float g_P[NSEG * DDOM * FDIM];     // partial sum(x)
__device__ float g_Q[NSEG * DDOM * FDIM];     // partial sum(x*x)
__device__ int   g_c[NSEG * DDOM];            // per-seg domain counts
__device__ float g_A[DDOM * FDIM];            // gamma * inv
__device__ float g_B[DDOM * FDIM];            // beta - mean * gamma * inv
__device__ int   g_ctr1;                      // phase-1 done counter
__device__ int   g_ctr2;                      // phase-2 done counter
__device__ int   g_ctr3;                      // exit counter (resets state)

// int64-vs-int32 y detection (odd 32-bit words all zero over 32 values)
__device__ __forceinline__ int detect64(const int* __restrict__ y) {
    const int4* p = (const int4*)y;
    int acc = 0;
#pragma unroll
    for (int i = 0; i < 8; i++) { int4 a = p[i]; acc |= a.y | a.w; }
    return acc == 0;
}

__device__ __forceinline__ void spin_until(volatile int* p, int target) {
    if (threadIdx.x == 0) {
        while (*p < target) __nanosleep(128);
    }
    __syncthreads();       // block-wide order after the wait
    __threadfence();       // acquire: later reads see producers' data
}

#define ACCUM(v)                                        \
    s1.x += v.x; s1.y += v.y; s1.z += v.z; s1.w += v.w; \
    s2.x = fmaf(v.x, v.x, s2.x);                        \
    s2.y = fmaf(v.y, v.y, s2.y);                        \
    s2.z = fmaf(v.z, v.z, s2.z);                        \
    s2.w = fmaf(v.w, v.w, s2.w);

__global__ __launch_bounds__(256, 2)
void dsbn_fused(const float4* __restrict__ x4, const int* __restrict__ yi,
                const float* __restrict__ gamma, const float* __restrict__ beta,
                float4* __restrict__ o4, int n, int rlo, int rem) {
    __shared__ int lst[DDOM][MAXR];   // prescaled row offsets (row * FV)
    __shared__ int cnt[DDOM];
    __shared__ float4 smP[8][32];
    __shared__ float4 smQ[8][32];
    __shared__ int    scnt[256];

    const int tid  = threadIdx.x;
    const int b    = blockIdx.x;
    const int base = b * rlo + min(b, rem);
    const int nrow = rlo + (b < rem ? 1 : 0);
    const int rend = min(base + nrow, n);

    // ================= Phase 1: segment stats =================
    if (tid < DDOM) cnt[tid] = 0;
    __syncthreads();

    if (tid < 32) {                   // warp 0: deterministic concat sort
        const int is64 = detect64(yi);
        for (int t0 = base; t0 < rend; t0 += 32) {
            const int r = t0 + tid;
            int d = -1;
            if (r < rend) d = is64 ? yi[2 * r] : yi[r];
            unsigned m = __match_any_sync(0xffffffffu, d);
            int rank = __popc(m & ((1u << tid) - 1u));
            int off = (d >= 0) ? cnt[d] : 0;
            __syncwarp();
            if (d >= 0) {
                lst[d][off + rank] = r * FV;
                if (rank == 0) cnt[d] = off + __popc(m);
            }
            __syncwarp();
        }
    }
    __syncthreads();

#pragma unroll
    for (int d = 0; d < DDOM; d++) {
        const int nd = cnt[d];
        float4 s1 = make_float4(0.f, 0.f, 0.f, 0.f);
        float4 s2 = make_float4(0.f, 0.f, 0.f, 0.f);
        int i = 0;
        for (; i + 4 <= nd; i += 4) {
            float4 v0 = __ldcg(x4 + lst[d][i]     + tid);
            float4 v1 = __ldcg(x4 + lst[d][i + 1] + tid);
            float4 v2 = __ldcg(x4 + lst[d][i + 2] + tid);
            float4 v3 = __ldcg(x4 + lst[d][i + 3] + tid);
            ACCUM(v0); ACCUM(v1); ACCUM(v2); ACCUM(v3);
        }
        for (; i < nd; i++) {
            float4 v = __ldcg(x4 + lst[d][i] + tid);
            ACCUM(v);
        }
        const size_t o = ((size_t)b * DDOM + d) * FV + tid;
        ((float4*)g_P)[o] = s1;
        ((float4*)g_Q)[o] = s2;
    }
    if (tid < DDOM) g_c[b * DDOM + tid] = cnt[tid];
    __syncthreads();
    if (tid == 0) {
        __threadfence();              // release partials
        atomicAdd(&g_ctr1, 1);
    }

    // ================= Phase 2: finalize (blocks 0..63) =================
    if (b < 64) {
        spin_until(&g_ctr1, NSEG);

        const int d  = b >> 3;
        const int fs = b & 7;
        const int w  = tid >> 5, lane = tid & 31;
        const int posIdx = fs * 32 + lane;        // f4 index 0..255

        {   // domain count
            int c = 0;
            for (int s = tid; s < NSEG; s += 256) c += g_c[s * DDOM + d];
            scnt[tid] = c;
        }

        const float4* P4 = (const float4*)g_P;
        const float4* Q4 = (const float4*)g_Q;
        float4 ap = make_float4(0.f, 0.f, 0.f, 0.f);
        float4 aq = make_float4(0.f, 0.f, 0.f, 0.f);
        int s = w;
        for (; s + 8 < NSEG; s += 16) {
            const size_t o0 = ((size_t)s * DDOM + d) * FV + posIdx;
            const size_t o1 = ((size_t)(s + 8) * DDOM + d) * FV + posIdx;
            float4 p0 = P4[o0], q0 = Q4[o0];
            float4 p1 = P4[o1], q1 = Q4[o1];
            ap.x += p0.x + p1.x; ap.y += p0.y + p1.y;
            ap.z += p0.z + p1.z; ap.w += p0.w + p1.w;
            aq.x += q0.x + q1.x; aq.y += q0.y + q1.y;
            aq.z += q0.z + q1.z; aq.w += q0.w + q1.w;
        }
        for (; s < NSEG; s += 8) {
            const size_t o = ((size_t)s * DDOM + d) * FV + posIdx;
            float4 p = P4[o], q = Q4[o];
            ap.x += p.x; ap.y += p.y; ap.z += p.z; ap.w += p.w;
            aq.x += q.x; aq.y += q.y; aq.z += q.z; aq.w += q.w;
        }
        smP[w][lane] = ap;
        smQ[w][lane] = aq;
        __syncthreads();

        for (int off = 128; off > 0; off >>= 1) {
            if (tid < off) scnt[tid] += scnt[tid + off];
            __syncthreads();
        }
        const float c = (float)scnt[0];

        if (w == 0) {
            float4 s1 = smP[0][lane], s2 = smQ[0][lane];
#pragma unroll
            for (int ww = 1; ww < 8; ww++) {
                float4 p = smP[ww][lane], q = smQ[ww][lane];
                s1.x += p.x; s1.y += p.y; s1.z += p.z; s1.w += p.w;
                s2.x += q.x; s2.y += q.y; s2.z += q.z; s2.w += q.w;
            }
            const int o = d * FDIM + posIdx * 4;
            float4 A, Bv;
            if (c > 1.5f) {
                const float rc = 1.0f / c;
                float4 g  = *(const float4*)(gamma + o);
                float4 be = *(const float4*)(beta + o);
                float mx = s1.x * rc, my = s1.y * rc, mz = s1.z * rc, mw = s1.w * rc;
                float vx = fmaf(-mx, mx, s2.x * rc);
                float vy = fmaf(-my, my, s2.y * rc);
                float vz = fmaf(-mz, mz, s2.z * rc);
                float vw = fmaf(-mw, mw, s2.w * rc);
                A.x = g.x * rsqrtf(vx + EPSV);
                A.y = g.y * rsqrtf(vy + EPSV);
                A.z = g.z * rsqrtf(vz + EPSV);
                A.w = g.w * rsqrtf(vw + EPSV);
                Bv.x = fmaf(-mx, A.x, be.x);
                Bv.y = fmaf(-my, A.y, be.y);
                Bv.z = fmaf(-mz, A.z, be.z);
                Bv.w = fmaf(-mw, A.w, be.w);
            } else if (c > 0.5f) {   // single-sample domain: out = x
                A  = make_float4(1.f, 1.f, 1.f, 1.f);
                Bv = make_float4(0.f, 0.f, 0.f, 0.f);
            } else {                 // empty domain (unused)
                A  = make_float4(0.f, 0.f, 0.f, 0.f);
                Bv = make_float4(0.f, 0.f, 0.f, 0.f);
            }
            *(float4*)(g_A + o) = A;
            *(float4*)(g_B + o) = Bv;
        }
        __syncthreads();
        if (tid == 0) {
            __threadfence();          // release A/B
            atomicAdd(&g_ctr2, 1);
        }
    }

    // ================= Phase 3: apply own segment =================
    spin_until(&g_ctr2, 64);

    const float4* A4 = (const float4*)g_A;
    const float4* B4 = (const float4*)g_B;

#pragma unroll
    for (int d = 0; d < DDOM; d++) {
        const int nd = cnt[d];
        if (nd == 0) continue;
        const float4 a  = __ldg(A4 + d * FV + tid);
        const float4 bb = __ldg(B4 + d * FV + tid);
        int i = 0;
        for (; i + 4 <= nd; i += 4) {
            const int r0 = lst[d][i], r1 = lst[d][i + 1];
            const int r2 = lst[d][i + 2], r3 = lst[d][i + 3];
            float4 v0 = __ldcs(x4 + r0 + tid);
            float4 v1 = __ldcs(x4 + r1 + tid);
            float4 v2 = __ldcs(x4 + r2 + tid);
            float4 v3 = __ldcs(x4 + r3 + tid);
            float4 w0, w1, w2, w3;
            w0.x = fmaf(v0.x, a.x, bb.x); w0.y = fmaf(v0.y, a.y, bb.y);
            w0.z = fmaf(v0.z, a.z, bb.z); w0.w = fmaf(v0.w, a.w, bb.w);
            w1.x = fmaf(v1.x, a.x, bb.x); w1.y = fmaf(v1.y, a.y, bb.y);
            w1.z = fmaf(v1.z, a.z, bb.z); w1.w = fmaf(v1.w, a.w, bb.w);
            w2.x = fmaf(v2.x, a.x, bb.x); w2.y = fmaf(v2.y, a.y, bb.y);
            w2.z = fmaf(v2.z, a.z, bb.z); w2.w = fmaf(v2.w, a.w, bb.w);
            w3.x = fmaf(v3.x, a.x, bb.x); w3.y = fmaf(v3.y, a.y, bb.y);
            w3.z = fmaf(v3.z, a.z, bb.z); w3.w = fmaf(v3.w, a.w, bb.w);
            __stcs(o4 + r0 + tid, w0);
            __stcs(o4 + r1 + tid, w1);
            __stcs(o4 + r2 + tid, w2);
            __stcs(o4 + r3 + tid, w3);
        }
        for (; i < nd; i++) {
            const int r = lst[d][i];
            float4 v = __ldcs(x4 + r + tid);
            float4 w;
            w.x = fmaf(v.x, a.x, bb.x); w.y = fmaf(v.y, a.y, bb.y);
            w.z = fmaf(v.z, a.z, bb.z); w.w = fmaf(v.w, a.w, bb.w);
            __stcs(o4 + r + tid, w);
        }
    }

    // ================= exit: last block resets counters =================
    __syncthreads();
    if (tid == 0) {
        __threadfence();
        int v = atomicAdd(&g_ctr3, 1);
        if (v == NSEG - 1) {          // everyone arrived; safe to reset
            g_ctr1 = 0;
            g_ctr2 = 0;
            g_ctr3 = 0;
            __threadfence();
        }
    }
}

extern "C" void kernel_launch(void* const* d_in, const int* in_sizes, int n_in,
                              void* d_out, int out_size) {
    const float* x     = (const float*)d_in[0];
    const int*   y     = (const int*)d_in[1];
    const float* gamma = (const float*)d_in[2];
    const float* beta  = (const float*)d_in[3];
    float* out = (float*)d_out;

    const int n   = in_sizes[1];
    const int rlo = n / NSEG;
    const int rem = n - rlo * NSEG;

    dsbn_fused<<<NSEG, 256>>>((const float4*)x, y, gamma, beta,
                              (float4*)out, n, rlo, rem);
}

// round 9
// speedup vs baseline: 1.2362x; 1.2362x over previous
#include <cuda_runtime.h>
#include <cstdint>

#define FDIM   1024
#define FV     256            // float4 per row
#define DDOM   8
#define MAXN   16384
#define NSEG   296            // 2 full waves on 148 SMs
#define MAXR   64             // max rows per segment (56)
#define DEPTH  10             // cp.async pipeline depth (rows in flight)
#define RA     8              // rows per apply block
#define EPSV   1e-5f

// ---------------- scratch ----------------
__device__ float g_P[NSEG * DDOM * FDIM];     // partial sum(x)
__device__ float g_Q[NSEG * DDOM * FDIM];     // partial sum(x*x)
__device__ int   g_c[NSEG * DDOM];            // per-seg domain counts
__device__ unsigned char g_ydom[MAXN];        // decoded domain per row
__device__ float g_A[DDOM * FDIM];            // gamma * inv
__device__ float g_B[DDOM * FDIM];            // beta - mean * gamma * inv

// int64-vs-int32 y detection (odd 32-bit words all zero over 32 values)
__device__ __forceinline__ int detect64(const int* __restrict__ y) {
    const int4* p = (const int4*)y;
    int acc = 0;
#pragma unroll
    for (int i = 0; i < 8; i++) { int4 a = p[i]; acc |= a.y | a.w; }
    return acc == 0;
}

#define ACCUM(v)                                        \
    s1.x += v.x; s1.y += v.y; s1.z += v.z; s1.w += v.w; \
    s2.x = fmaf(v.x, v.x, s2.x);                        \
    s2.y = fmaf(v.y, v.y, s2.y);                        \
    s2.z = fmaf(v.z, v.z, s2.z);                        \
    s2.w = fmaf(v.w, v.w, s2.w);

// ---- K1: stats via deep cp.async pipeline over domain-sorted flat list ----
__global__ __launch_bounds__(256, 2)
void stats_k(const float4* __restrict__ x4, const int* __restrict__ yi,
             int n, int rlo, int rem) {
    __shared__ float4 buf[DEPTH][256];   // 40 KB ring of row buffers
    __shared__ int flat[MAXR];           // row*FV, domain-sorted
    __shared__ int cnt[DDOM];            // total rows per domain
    __shared__ int fill[DDOM];           // placement cursors

    const int tid  = threadIdx.x;
    const int b    = blockIdx.x;
    const int base = b * rlo + min(b, rem);
    const int nr   = min(rlo + (b < rem ? 1 : 0), n - base);

    if (tid < DDOM) cnt[tid] = 0;
    __syncthreads();

    if (tid < 32) {   // warp 0: deterministic 2-tile counting sort -> flat[]
        const int is64 = detect64(yi);
        const int r0 = base + tid;
        const int r1 = base + 32 + tid;
        const int da = (tid < nr)      ? (is64 ? yi[2 * r0] : yi[r0]) : -1;
        const int db = (32 + tid < nr) ? (is64 ? yi[2 * r1] : yi[r1]) : -1;
        const unsigned ma = __match_any_sync(0xffffffffu, da);
        if (da >= 0) {
            g_ydom[r0] = (unsigned char)da;
            if ((int)(__ffs(ma) - 1) == tid) cnt[da] = __popc(ma);
        }
        __syncwarp();
        const unsigned mb = __match_any_sync(0xffffffffu, db);
        if (db >= 0) {
            g_ydom[r1] = (unsigned char)db;
            if ((int)(__ffs(mb) - 1) == tid) cnt[db] += __popc(mb);
        }
        __syncwarp();
        if (tid == 0) {
            int run = 0;
#pragma unroll
            for (int d = 0; d < DDOM; d++) { fill[d] = run; run += cnt[d]; }
        }
        __syncwarp();
        const int ra = __popc(ma & ((1u << tid) - 1u));
        if (da >= 0) flat[fill[da] + ra] = r0 * FV;
        __syncwarp();
        if (da >= 0 && (int)(__ffs(ma) - 1) == tid) fill[da] += __popc(ma);
        __syncwarp();
        const int rb = __popc(mb & ((1u << tid) - 1u));
        if (db >= 0) flat[fill[db] + rb] = r1 * FV;
    }
    __syncthreads();

    // smem byte address of buf for cp.async
    uint32_t sbuf;
    asm("{ .reg .u64 t; cvta.to.shared.u64 t, %1; cvt.u32.u64 %0, t; }"
        : "=r"(sbuf) : "l"(buf));
    const char* xb = (const char*)x4;
    const uint32_t myoff = tid * 16;

#define ISSUE(k) do {                                                        \
        uint32_t _da = sbuf + ((k) % DEPTH) * 4096 + myoff;                  \
        const void* _g = xb + ((size_t)(flat[(k)] + tid) << 4);              \
        asm volatile("cp.async.cg.shared.global [%0], [%1], 16;"             \
                     :: "r"(_da), "l"(_g) : "memory");                       \
        asm volatile("cp.async.commit_group;" ::: "memory");                 \
    } while (0)

    const int np = min(DEPTH, nr);
    for (int k = 0; k < np; k++) ISSUE(k);
    int issued = np;
    int i = 0;

#pragma unroll
    for (int d = 0; d < DDOM; d++) {
        const int nd = cnt[d];
        float4 s1 = make_float4(0.f, 0.f, 0.f, 0.f);
        float4 s2 = make_float4(0.f, 0.f, 0.f, 0.f);
        for (int k = 0; k < nd; k++, i++) {
            if (issued < nr) {
                asm volatile("cp.async.wait_group %0;" :: "n"(DEPTH - 1) : "memory");
            } else {
                asm volatile("cp.async.wait_group 0;" ::: "memory");
            }
            float4 v = buf[i % DEPTH][tid];     // consume slot
            if (issued < nr) { ISSUE(issued); issued++; }  // then refill it
            ACCUM(v);
        }
        const size_t o = ((size_t)b * DDOM + d) * FV + tid;
        ((float4*)g_P)[o] = s1;
        ((float4*)g_Q)[o] = s2;
    }
    if (tid < DDOM) g_c[b * DDOM + tid] = cnt[tid];
#undef ISSUE
}

// ---- K2: fold segments -> A/B. grid = 64 blocks (8 dom x 8 f4-slices). ----
__global__ __launch_bounds__(256)
void finalize_k(const float* __restrict__ gamma, const float* __restrict__ beta,
                int nseg) {
    __shared__ float4 smP[8][32];
    __shared__ float4 smQ[8][32];
    __shared__ int    scnt[256];
    const int tid  = threadIdx.x;
    const int d    = blockIdx.x >> 3;
    const int fs   = blockIdx.x & 7;
    const int w    = tid >> 5, lane = tid & 31;
    const int posIdx = fs * 32 + lane;

    {
        int c = 0;
        for (int s = tid; s < nseg; s += 256) c += g_c[s * DDOM + d];
        scnt[tid] = c;
    }

    const float4* P4 = (const float4*)g_P;
    const float4* Q4 = (const float4*)g_Q;
    float4 ap = make_float4(0.f, 0.f, 0.f, 0.f);
    float4 aq = make_float4(0.f, 0.f, 0.f, 0.f);
    int s = w;
    for (; s + 8 < nseg; s += 16) {
        const size_t o0 = ((size_t)s * DDOM + d) * FV + posIdx;
        const size_t o1 = ((size_t)(s + 8) * DDOM + d) * FV + posIdx;
        float4 p0 = P4[o0], q0 = Q4[o0];
        float4 p1 = P4[o1], q1 = Q4[o1];
        ap.x += p0.x + p1.x; ap.y += p0.y + p1.y;
        ap.z += p0.z + p1.z; ap.w += p0.w + p1.w;
        aq.x += q0.x + q1.x; aq.y += q0.y + q1.y;
        aq.z += q0.z + q1.z; aq.w += q0.w + q1.w;
    }
    for (; s < nseg; s += 8) {
        const size_t o = ((size_t)s * DDOM + d) * FV + posIdx;
        float4 p = P4[o], q = Q4[o];
        ap.x += p.x; ap.y += p.y; ap.z += p.z; ap.w += p.w;
        aq.x += q.x; aq.y += q.y; aq.z += q.z; aq.w += q.w;
    }
    smP[w][lane] = ap;
    smQ[w][lane] = aq;
    __syncthreads();

    for (int off = 128; off > 0; off >>= 1) {
        if (tid < off) scnt[tid] += scnt[tid + off];
        __syncthreads();
    }
    const float c = (float)scnt[0];

    if (w == 0) {
        float4 s1 = smP[0][lane], s2 = smQ[0][lane];
#pragma unroll
        for (int ww = 1; ww < 8; ww++) {
            float4 p = smP[ww][lane], q = smQ[ww][lane];
            s1.x += p.x; s1.y += p.y; s1.z += p.z; s1.w += p.w;
            s2.x += q.x; s2.y += q.y; s2.z += q.z; s2.w += q.w;
        }
        const int o = d * FDIM + posIdx * 4;
        float4 A, Bv;
        if (c > 1.5f) {
            const float rc = 1.0f / c;
            float4 g  = *(const float4*)(gamma + o);
            float4 be = *(const float4*)(beta + o);
            float mx = s1.x * rc, my = s1.y * rc, mz = s1.z * rc, mw = s1.w * rc;
            float vx = fmaf(-mx, mx, s2.x * rc);
            float vy = fmaf(-my, my, s2.y * rc);
            float vz = fmaf(-mz, mz, s2.z * rc);
            float vw = fmaf(-mw, mw, s2.w * rc);
            A.x = g.x * rsqrtf(vx + EPSV);
            A.y = g.y * rsqrtf(vy + EPSV);
            A.z = g.z * rsqrtf(vz + EPSV);
            A.w = g.w * rsqrtf(vw + EPSV);
            Bv.x = fmaf(-mx, A.x, be.x);
            Bv.y = fmaf(-my, A.y, be.y);
            Bv.z = fmaf(-mz, A.z, be.z);
            Bv.w = fmaf(-mw, A.w, be.w);
        } else if (c > 0.5f) {   // single-sample domain: out = x
            A  = make_float4(1.f, 1.f, 1.f, 1.f);
            Bv = make_float4(0.f, 0.f, 0.f, 0.f);
        } else {                 // empty domain (unused)
            A  = make_float4(0.f, 0.f, 0.f, 0.f);
            Bv = make_float4(0.f, 0.f, 0.f, 0.f);
        }
        *(float4*)(g_A + o) = A;
        *(float4*)(g_B + o) = Bv;
    }
}

// ---------------- K3: out = A[d]*x + B[d] ----------------
__global__ __launch_bounds__(256)
void apply_k(const float4* __restrict__ x4, float4* __restrict__ o4, int n) {
    __shared__ int sd[RA];
    const int tid = threadIdx.x;
    const int r0  = blockIdx.x * RA;

    if (tid < RA) {
        const int r = r0 + tid;
        sd[tid] = (r < n) ? (int)g_ydom[r] : 0;
    }
    __syncthreads();

    const float4* A4 = (const float4*)g_A;
    const float4* B4 = (const float4*)g_B;

#pragma unroll
    for (int j = 0; j < RA; j += 4) {
        const int r = r0 + j;
        if (r + 3 < n) {
            const int d0 = sd[j], d1 = sd[j + 1], d2 = sd[j + 2], d3 = sd[j + 3];
            const float4* p = x4 + (size_t)r * FV + tid;
            float4 v0 = __ldcs(p);
            float4 v1 = __ldcs(p + FV);
            float4 v2 = __ldcs(p + 2 * FV);
            float4 v3 = __ldcs(p + 3 * FV);
            float4 a0 = __ldg(A4 + d0 * FV + tid);
            float4 b0 = __ldg(B4 + d0 * FV + tid);
            float4 a1 = __ldg(A4 + d1 * FV + tid);
            float4 b1 = __ldg(B4 + d1 * FV + tid);
            float4 a2 = __ldg(A4 + d2 * FV + tid);
            float4 b2 = __ldg(B4 + d2 * FV + tid);
            float4 a3 = __ldg(A4 + d3 * FV + tid);
            float4 b3 = __ldg(B4 + d3 * FV + tid);
            float4 w0, w1, w2, w3;
            w0.x = fmaf(v0.x, a0.x, b0.x); w0.y = fmaf(v0.y, a0.y, b0.y);
            w0.z = fmaf(v0.z, a0.z, b0.z); w0.w = fmaf(v0.w, a0.w, b0.w);
            w1.x = fmaf(v1.x, a1.x, b1.x); w1.y = fmaf(v1.y, a1.y, b1.y);
            w1.z = fmaf(v1.z, a1.z, b1.z); w1.w = fmaf(v1.w, a1.w, b1.w);
            w2.x = fmaf(v2.x, a2.x, b2.x); w2.y = fmaf(v2.y, a2.y, b2.y);
            w2.z = fmaf(v2.z, a2.z, b2.z); w2.w = fmaf(v2.w, a2.w, b2.w);
            w3.x = fmaf(v3.x, a3.x, b3.x); w3.y = fmaf(v3.y, a3.y, b3.y);
            w3.z = fmaf(v3.z, a3.z, b3.z); w3.w = fmaf(v3.w, a3.w, b3.w);
            float4* q = o4 + (size_t)r * FV + tid;
            __stcs(q,          w0);
            __stcs(q + FV,     w1);
            __stcs(q + 2 * FV, w2);
            __stcs(q + 3 * FV, w3);
        } else {
            for (int k = 0; k < 4; k++) {
                const int rr = r + k;
                if (rr >= n) break;
                const int dd = sd[j + k];
                float4 v = __ldcs(x4 + (size_t)rr * FV + tid);
                float4 a = __ldg(A4 + dd * FV + tid);
                float4 b = __ldg(B4 + dd * FV + tid);
                float4 w;
                w.x = fmaf(v.x, a.x, b.x); w.y = fmaf(v.y, a.y, b.y);
                w.z = fmaf(v.z, a.z, b.z); w.w = fmaf(v.w, a.w, b.w);
                __stcs(o4 + (size_t)rr * FV + tid, w);
            }
        }
    }
}

extern "C" void kernel_launch(void* const* d_in, const int* in_sizes, int n_in,
                              void* d_out, int out_size) {
    const float* x     = (const float*)d_in[0];
    const int*   y     = (const int*)d_in[1];
    const float* gamma = (const float*)d_in[2];
    const float* beta  = (const float*)d_in[3];
    float* out = (float*)d_out;

    const int n   = in_sizes[1];
    const int rlo = n / NSEG;
    const int rem = n - rlo * NSEG;

    stats_k<<<NSEG, 256>>>((const float4*)x, y, n, rlo, rem);
    finalize_k<<<DDOM * 8, 256>>>(gamma, beta, NSEG);
    apply_k<<<(n + RA - 1) / RA, 256>>>((const float4*)x, (float4*)out, n);
}